// round 2
// baseline (speedup 1.0000x reference)
#include <cuda_runtime.h>
#include <cuda_bf16.h>
#include <cstdint>

// Problem constants
#define NB 16
#define CH 64
#define LL 4096   // H*W
#define DD 1024   // pooled locations
#define CK 8      // C>>3 (theta/phi channels)
#define CG 32     // C>>1 (g channels)

// Scratch (device globals; no allocation allowed). 16B-aligned for float4 access.
__device__ __align__(16) float g_theta[NB * LL * CK];   // [n][l][k], pre-scaled by log2(e)
__device__ __align__(16) float g_phiT[NB * CK * DD];    // [n][k][d]
__device__ __align__(16) float g_gT[NB * CG * DD];      // [n][j][d]

typedef unsigned long long ull;

__device__ __forceinline__ ull pk2(float a, float b) {
    ull r; asm("mov.b64 %0, {%1, %2};" : "=l"(r) : "f"(a), "f"(b)); return r;
}
__device__ __forceinline__ float2 upk2(ull v) {
    float2 r; asm("mov.b64 {%0, %1}, %2;" : "=f"(r.x), "=f"(r.y) : "l"(v)); return r;
}
__device__ __forceinline__ ull fma2(ull a, ull b, ull c) {
    ull d; asm("fma.rn.f32x2 %0, %1, %2, %3;" : "=l"(d) : "l"(a), "l"(b), "l"(c)); return d;
}
__device__ __forceinline__ ull add2(ull a, ull b) {
    ull d; asm("add.rn.f32x2 %0, %1, %2;" : "=l"(d) : "l"(a), "l"(b)); return d;
}
__device__ __forceinline__ float ex2f(float x) {
    float r; asm("ex2.approx.ftz.f32 %0, %1;" : "=f"(r) : "f"(x)); return r;
}

// ---------------------------------------------------------------------------
// Kernel A: theta projection.  theta[n][l][k] = log2(e) * sum_c w_theta[k][c]*x[n][c][l]
// 256 blocks x 256 threads, one thread per (n,l).
// ---------------------------------------------------------------------------
__global__ void __launch_bounds__(256) proj_theta_kernel(
        const float* __restrict__ x, const float* __restrict__ w_theta) {
    __shared__ float ws[CK * CH];   // 512 floats
    int tid = threadIdx.x;
    for (int i = tid; i < CK * CH; i += 256)            // FIXED: strided fill
        ws[i] = w_theta[i] * 1.4426950408889634f;
    __syncthreads();

    int idx = blockIdx.x * 256 + tid;      // n*LL + l
    int n = idx >> 12;
    int l = idx & (LL - 1);
    const float* xp = x + ((size_t)n * CH) * LL + l;

    float acc[CK];
#pragma unroll
    for (int k = 0; k < CK; k++) acc[k] = 0.f;
#pragma unroll 8
    for (int c = 0; c < CH; c++) {
        float xv = xp[(size_t)c * LL];
#pragma unroll
        for (int k = 0; k < CK; k++) acc[k] = fmaf(ws[k * CH + c], xv, acc[k]);
    }
    float4* tp = (float4*)(g_theta + (size_t)idx * CK);
    tp[0] = make_float4(acc[0], acc[1], acc[2], acc[3]);
    tp[1] = make_float4(acc[4], acc[5], acc[6], acc[7]);
}

// ---------------------------------------------------------------------------
// Kernel B: pooled phi and g projections.
// phi[n][k][d] = max over 2x2 of (w_phi @ x);   g[n][j][d] = max over 2x2 of (w_g @ x)
// 64 blocks x 256 threads, one thread per (n,d).
// ---------------------------------------------------------------------------
__global__ void __launch_bounds__(256) proj_pool_kernel(
        const float* __restrict__ x,
        const float* __restrict__ w_phi, const float* __restrict__ w_g) {
    __shared__ float wps[CK * CH];    // 512
    __shared__ float wgs[CG * CH];    // 2048
    int tid = threadIdx.x;
    for (int i = tid; i < CK * CH; i += 256) wps[i] = w_phi[i];   // FIXED: strided fill
    for (int i = tid; i < CG * CH; i += 256) wgs[i] = w_g[i];
    __syncthreads();

    int idx = blockIdx.x * 256 + tid;      // n*DD + d
    int n = idx >> 10;
    int d = idx & (DD - 1);
    int dr = d >> 5, dc = d & 31;
    const float* xb = x + ((size_t)n * CH) * LL + (dr * 2) * 64 + dc * 2;

    float pphi[CK], pg[CG];
#pragma unroll
    for (int k = 0; k < CK; k++) pphi[k] = -3.0e38f;
#pragma unroll
    for (int j = 0; j < CG; j++) pg[j] = -3.0e38f;

#pragma unroll
    for (int p = 0; p < 4; p++) {
        const float* xp = xb + (p >> 1) * 64 + (p & 1);
        float ap[CK], ag[CG];
#pragma unroll
        for (int k = 0; k < CK; k++) ap[k] = 0.f;
#pragma unroll
        for (int j = 0; j < CG; j++) ag[j] = 0.f;
#pragma unroll 4
        for (int c = 0; c < CH; c++) {
            float xv = xp[(size_t)c * LL];
#pragma unroll
            for (int k = 0; k < CK; k++) ap[k] = fmaf(wps[k * CH + c], xv, ap[k]);
#pragma unroll
            for (int j = 0; j < CG; j++) ag[j] = fmaf(wgs[j * CH + c], xv, ag[j]);
        }
#pragma unroll
        for (int k = 0; k < CK; k++) pphi[k] = fmaxf(pphi[k], ap[k]);
#pragma unroll
        for (int j = 0; j < CG; j++) pg[j] = fmaxf(pg[j], ag[j]);
    }

    float* php = g_phiT + (size_t)n * CK * DD + d;
#pragma unroll
    for (int k = 0; k < CK; k++) php[(size_t)k * DD] = pphi[k];
    float* ggp = g_gT + (size_t)n * CG * DD + d;
#pragma unroll
    for (int j = 0; j < CG; j++) ggp[(size_t)j * DD] = pg[j];
}

// ---------------------------------------------------------------------------
// Kernel C: fused softmax attention + output projection + residual.
// Grid (16 L-tiles, 16 batches) x 256 threads; one thread per location l.
// SMEM: phi [8][1024] + g [32][1024] + w_o [64][32]  (172 KB).
// Inner loop processes 4 d-values/iter with fma.rn.f32x2 (pairs over d).
// ---------------------------------------------------------------------------
__global__ void __launch_bounds__(256, 1) attn_kernel(
        const float* __restrict__ x, const float* __restrict__ w_o,
        const float* __restrict__ gammap, float* __restrict__ out) {
    extern __shared__ float smem[];
    float* phs = smem;                       // CK*DD floats
    float* ggs = smem + CK * DD;             // CG*DD floats
    float* wos = smem + (CK + CG) * DD;      // CH*CG floats

    int tid = threadIdx.x;
    int n = blockIdx.y;

    // Cooperative SMEM fills (float4)
    {
        const float4* s1 = (const float4*)(g_phiT + (size_t)n * CK * DD);
        float4* d1 = (float4*)phs;
        for (int i = tid; i < CK * DD / 4; i += 256) d1[i] = s1[i];
        const float4* s2 = (const float4*)(g_gT + (size_t)n * CG * DD);
        float4* d2 = (float4*)ggs;
        for (int i = tid; i < CG * DD / 4; i += 256) d2[i] = s2[i];
        const float4* s3 = (const float4*)w_o;
        float4* d3 = (float4*)wos;
        for (int i = tid; i < CH * CG / 4; i += 256) d3[i] = s3[i];
    }

    int l = blockIdx.x * 256 + tid;

    // theta (pre-scaled by log2 e) -> duplicated pairs for f32x2
    ull tk2[CK];
    {
        const float4* tp = (const float4*)(g_theta + ((size_t)n * LL + l) * CK);
        float4 t0 = tp[0], t1 = tp[1];
        tk2[0] = pk2(t0.x, t0.x); tk2[1] = pk2(t0.y, t0.y);
        tk2[2] = pk2(t0.z, t0.z); tk2[3] = pk2(t0.w, t0.w);
        tk2[4] = pk2(t1.x, t1.x); tk2[5] = pk2(t1.y, t1.y);
        tk2[6] = pk2(t1.z, t1.z); tk2[7] = pk2(t1.w, t1.w);
    }
    __syncthreads();

    ull acc[CG];
#pragma unroll
    for (int j = 0; j < CG; j++) acc[j] = 0ull;   // bit pattern {0.f, 0.f}
    ull se = 0ull;

    const ulonglong2* ph2 = (const ulonglong2*)phs;   // [CK][DD/4]
    const ulonglong2* gg2 = (const ulonglong2*)ggs;   // [CG][DD/4]

#pragma unroll 1
    for (int q = 0; q < DD / 4; q++) {
        // logits for d = 4q..4q+3
        ull s01 = 0ull, s23 = 0ull;
#pragma unroll
        for (int k = 0; k < CK; k++) {
            ulonglong2 pv = ph2[k * (DD / 4) + q];
            s01 = fma2(tk2[k], pv.x, s01);
            s23 = fma2(tk2[k], pv.y, s23);
        }
        float2 sa = upk2(s01), sb = upk2(s23);
        ull e01 = pk2(ex2f(sa.x), ex2f(sa.y));
        ull e23 = pk2(ex2f(sb.x), ex2f(sb.y));
        se = add2(se, add2(e01, e23));
#pragma unroll
        for (int j = 0; j < CG; j++) {
            ulonglong2 gv = gg2[j * (DD / 4) + q];
            acc[j] = fma2(e01, gv.x, acc[j]);
            acc[j] = fma2(e23, gv.y, acc[j]);
        }
    }

    float2 sef = upk2(se);
    float inv = 1.0f / (sef.x + sef.y);

    // normalized attn_g values, repacked as pairs over g-channel
    ull rp[CG / 2];
#pragma unroll
    for (int j = 0; j < CG; j += 2) {
        float2 a = upk2(acc[j]);
        float2 b = upk2(acc[j + 1]);
        rp[j >> 1] = pk2((a.x + a.y) * inv, (b.x + b.y) * inv);
    }

    float gamma = *gammap;
    const float* xp = x + ((size_t)n * CH) * LL + l;
    float* op = out + ((size_t)n * CH) * LL + l;
    const ulonglong2* w2 = (const ulonglong2*)wos;    // [CH][CG/4]

#pragma unroll 4
    for (int oc = 0; oc < CH; oc++) {
        ull s2 = 0ull;
#pragma unroll
        for (int q = 0; q < CG / 4; q++) {
            ulonglong2 wv = w2[oc * (CG / 4) + q];
            s2 = fma2(rp[2 * q], wv.x, s2);
            s2 = fma2(rp[2 * q + 1], wv.y, s2);
        }
        float2 sf = upk2(s2);
        op[(size_t)oc * LL] = fmaf(gamma, sf.x + sf.y, xp[(size_t)oc * LL]);
    }
}

// ---------------------------------------------------------------------------
extern "C" void kernel_launch(void* const* d_in, const int* in_sizes, int n_in,
                              void* d_out, int out_size) {
    const float* x       = (const float*)d_in[0];
    const float* w_theta = (const float*)d_in[1];
    const float* w_phi   = (const float*)d_in[2];
    const float* w_g     = (const float*)d_in[3];
    const float* w_o     = (const float*)d_in[4];
    const float* gammap  = (const float*)d_in[5];
    float* out = (float*)d_out;

    const int smem_bytes = ((CK + CG) * DD + CH * CG) * (int)sizeof(float); // 172032
    cudaFuncSetAttribute(attn_kernel, cudaFuncAttributeMaxDynamicSharedMemorySize,
                         smem_bytes);

    proj_theta_kernel<<<NB * LL / 256, 256>>>(x, w_theta);
    proj_pool_kernel<<<NB * DD / 256, 256>>>(x, w_phi, w_g);
    dim3 grid(LL / 256, NB);
    attn_kernel<<<grid, 256, smem_bytes>>>(x, w_o, gammap, out);
}

// round 3
// speedup vs baseline: 1.3585x; 1.3585x over previous
#include <cuda_runtime.h>
#include <cuda_bf16.h>
#include <cstdint>

// Problem constants
#define NB 16
#define CH 64
#define LL 4096   // H*W
#define DD 1024   // pooled locations
#define CK 8      // C>>3 (theta/phi channels)
#define CG 32     // C>>1 (g channels)

typedef unsigned long long ull;

// Scratch (device globals; no allocation allowed). 16B-aligned.
__device__ __align__(16) float g_theta[NB * LL * CK];        // [n][l][k], pre-scaled by log2(e)
__device__ __align__(16) float g_phiT[NB * CK * DD];         // [n][k][d]
__device__ __align__(16) ull   g_gT2[NB * DD * (CG / 2)];    // [n][d][jp], pair {g[2j],g[2j+1]}

__device__ __forceinline__ ull pk2(float a, float b) {
    ull r; asm("mov.b64 %0, {%1, %2};" : "=l"(r) : "f"(a), "f"(b)); return r;
}
__device__ __forceinline__ float2 upk2(ull v) {
    float2 r; asm("mov.b64 {%0, %1}, %2;" : "=f"(r.x), "=f"(r.y) : "l"(v)); return r;
}
__device__ __forceinline__ ull fma2(ull a, ull b, ull c) {
    ull d; asm("fma.rn.f32x2 %0, %1, %2, %3;" : "=l"(d) : "l"(a), "l"(b), "l"(c)); return d;
}
__device__ __forceinline__ ull mul2(ull a, ull b) {
    ull d; asm("mul.rn.f32x2 %0, %1, %2;" : "=l"(d) : "l"(a), "l"(b)); return d;
}
__device__ __forceinline__ float ex2f(float x) {
    float r; asm("ex2.approx.ftz.f32 %0, %1;" : "=f"(r) : "f"(x)); return r;
}

// ---------------------------------------------------------------------------
// Kernel A: theta projection, 2 locations/thread via f32x2.
// theta[n][l][k] = log2(e) * sum_c w_theta[k][c] * x[n][c][l]
// 128 blocks x 256 threads; thread -> (n, l0=2*lpair).
// ---------------------------------------------------------------------------
__global__ void __launch_bounds__(256) proj_theta_kernel(
        const float* __restrict__ x, const float* __restrict__ w_theta) {
    __shared__ ull ws2[CK * CH];   // duplicated-pair weights, pre-scaled
    int tid = threadIdx.x;
    for (int i = tid; i < CK * CH; i += 256) {
        float w = w_theta[i] * 1.4426950408889634f;
        ws2[i] = pk2(w, w);
    }
    __syncthreads();

    int idx = blockIdx.x * 256 + tid;      // pair index: n*2048 + lpair
    int n = idx >> 11;
    int l0 = (idx & 2047) << 1;
    const float* xp = x + ((size_t)n * CH) * LL + l0;

    ull acc[CK];
#pragma unroll
    for (int k = 0; k < CK; k++) acc[k] = 0ull;
#pragma unroll 16
    for (int c = 0; c < CH; c++) {
        float2 xv = *(const float2*)(xp + (size_t)c * LL);
        ull v = pk2(xv.x, xv.y);
#pragma unroll
        for (int k = 0; k < CK; k++) acc[k] = fma2(ws2[k * CH + c], v, acc[k]);
    }
    float2 t[CK];
#pragma unroll
    for (int k = 0; k < CK; k++) t[k] = upk2(acc[k]);

    float4* tp = (float4*)(g_theta + ((size_t)n * LL + l0) * CK);
    tp[0] = make_float4(t[0].x, t[1].x, t[2].x, t[3].x);
    tp[1] = make_float4(t[4].x, t[5].x, t[6].x, t[7].x);
    tp[2] = make_float4(t[0].y, t[1].y, t[2].y, t[3].y);
    tp[3] = make_float4(t[4].y, t[5].y, t[6].y, t[7].y);
}

// ---------------------------------------------------------------------------
// Kernel B: pooled phi and g projections, f32x2 over horizontal pixel pairs.
// 64 blocks x 256 threads, one thread per (n,d). g written pre-packed in j-pairs.
// ---------------------------------------------------------------------------
__global__ void __launch_bounds__(256) proj_pool_kernel(
        const float* __restrict__ x,
        const float* __restrict__ w_phi, const float* __restrict__ w_g) {
    __shared__ ull wps2[CK * CH];    // 4 KB
    __shared__ ull wgs2[CG * CH];    // 16 KB
    int tid = threadIdx.x;
    for (int i = tid; i < CK * CH; i += 256) { float w = w_phi[i]; wps2[i] = pk2(w, w); }
    for (int i = tid; i < CG * CH; i += 256) { float w = w_g[i];   wgs2[i] = pk2(w, w); }
    __syncthreads();

    int idx = blockIdx.x * 256 + tid;      // n*DD + d
    int n = idx >> 10;
    int d = idx & (DD - 1);
    int dr = d >> 5, dc = d & 31;
    const float* xp0 = x + ((size_t)n * CH) * LL + (dr * 2) * 64 + dc * 2;       // row 0
    const float* xp1 = xp0 + 64;                                                  // row 1

    ull ap0[CK], ap1[CK], ag0[CG], ag1[CG];
#pragma unroll
    for (int k = 0; k < CK; k++) { ap0[k] = 0ull; ap1[k] = 0ull; }
#pragma unroll
    for (int j = 0; j < CG; j++) { ag0[j] = 0ull; ag1[j] = 0ull; }

#pragma unroll 4
    for (int c = 0; c < CH; c++) {
        float2 x0 = *(const float2*)(xp0 + (size_t)c * LL);
        float2 x1 = *(const float2*)(xp1 + (size_t)c * LL);
        ull v0 = pk2(x0.x, x0.y);
        ull v1 = pk2(x1.x, x1.y);
#pragma unroll
        for (int k = 0; k < CK; k++) {
            ap0[k] = fma2(wps2[k * CH + c], v0, ap0[k]);
            ap1[k] = fma2(wps2[k * CH + c], v1, ap1[k]);
        }
#pragma unroll
        for (int j = 0; j < CG; j++) {
            ag0[j] = fma2(wgs2[j * CH + c], v0, ag0[j]);
            ag1[j] = fma2(wgs2[j * CH + c], v1, ag1[j]);
        }
    }

    // phi: 2x2 max, store [k][d] strided
    float* php = g_phiT + (size_t)n * CK * DD + d;
#pragma unroll
    for (int k = 0; k < CK; k++) {
        float2 a = upk2(ap0[k]), b = upk2(ap1[k]);
        php[(size_t)k * DD] = fmaxf(fmaxf(a.x, a.y), fmaxf(b.x, b.y));
    }
    // g: 2x2 max, store pre-packed j-pairs, contiguous 128B per d
    float pg[CG];
#pragma unroll
    for (int j = 0; j < CG; j++) {
        float2 a = upk2(ag0[j]), b = upk2(ag1[j]);
        pg[j] = fmaxf(fmaxf(a.x, a.y), fmaxf(b.x, b.y));
    }
    ulonglong2* dst = (ulonglong2*)(g_gT2 + ((size_t)n * DD + d) * (CG / 2));
#pragma unroll
    for (int p = 0; p < CG / 4; p++)
        dst[p] = make_ulonglong2(pk2(pg[4 * p], pg[4 * p + 1]),
                                 pk2(pg[4 * p + 2], pg[4 * p + 3]));
}

// ---------------------------------------------------------------------------
// Kernel C: fused softmax attention + output projection + residual.
// Grid (8 L-tiles, 16 batches) x 256 threads = 128 CTAs (single wave).
// Each thread owns 2 adjacent locations (l0, l0+1).
// SMEM: phi [8][1024]f + g2 [1024][16]ull + w_o [64][32]f  = 168 KB.
// ---------------------------------------------------------------------------
__global__ void __launch_bounds__(256, 1) attn_kernel(
        const float* __restrict__ x, const float* __restrict__ w_o,
        const float* __restrict__ gammap, float* __restrict__ out) {
    extern __shared__ float smem[];
    float* phs = smem;                                   // CK*DD floats (32 KB)
    ull*   g2s = (ull*)(smem + CK * DD);                 // DD*16 ull   (128 KB)
    float* wos = smem + CK * DD + DD * CG;               // CH*CG floats (8 KB)

    int tid = threadIdx.x;
    int n = blockIdx.y;

    // Cooperative SMEM fills (float4)
    {
        const float4* s1 = (const float4*)(g_phiT + (size_t)n * CK * DD);
        float4* d1 = (float4*)phs;
        for (int i = tid; i < CK * DD / 4; i += 256) d1[i] = s1[i];
        const float4* s2 = (const float4*)(g_gT2 + (size_t)n * DD * (CG / 2));
        float4* d2 = (float4*)g2s;
        for (int i = tid; i < DD * CG / 4; i += 256) d2[i] = s2[i];
        const float4* s3 = (const float4*)w_o;
        float4* d3 = (float4*)wos;
        for (int i = tid; i < CH * CG / 4; i += 256) d3[i] = s3[i];
    }

    int l0 = blockIdx.x * 512 + 2 * tid;

    // theta for both locations (pre-scaled by log2 e), duplicated pairs
    ull tkA[CK], tkB[CK];
    {
        const float4* tp = (const float4*)(g_theta + ((size_t)n * LL + l0) * CK);
        float4 a0 = tp[0], a1 = tp[1], b0 = tp[2], b1 = tp[3];
        tkA[0] = pk2(a0.x, a0.x); tkA[1] = pk2(a0.y, a0.y);
        tkA[2] = pk2(a0.z, a0.z); tkA[3] = pk2(a0.w, a0.w);
        tkA[4] = pk2(a1.x, a1.x); tkA[5] = pk2(a1.y, a1.y);
        tkA[6] = pk2(a1.z, a1.z); tkA[7] = pk2(a1.w, a1.w);
        tkB[0] = pk2(b0.x, b0.x); tkB[1] = pk2(b0.y, b0.y);
        tkB[2] = pk2(b0.z, b0.z); tkB[3] = pk2(b0.w, b0.w);
        tkB[4] = pk2(b1.x, b1.x); tkB[5] = pk2(b1.y, b1.y);
        tkB[6] = pk2(b1.z, b1.z); tkB[7] = pk2(b1.w, b1.w);
    }
    __syncthreads();

    ull accA[CG / 2], accB[CG / 2];
#pragma unroll
    for (int p = 0; p < CG / 2; p++) { accA[p] = 0ull; accB[p] = 0ull; }
    float seA = 0.f, seB = 0.f;

    const ulonglong2* ph2 = (const ulonglong2*)phs;   // [CK][DD/4]

#pragma unroll 1
    for (int q = 0; q < DD / 4; q++) {
        // logits for d = 4q..4q+3, both locations
        ull sA01 = 0ull, sA23 = 0ull, sB01 = 0ull, sB23 = 0ull;
#pragma unroll
        for (int k = 0; k < CK; k++) {
            ulonglong2 pv = ph2[k * (DD / 4) + q];
            sA01 = fma2(tkA[k], pv.x, sA01);
            sA23 = fma2(tkA[k], pv.y, sA23);
            sB01 = fma2(tkB[k], pv.x, sB01);
            sB23 = fma2(tkB[k], pv.y, sB23);
        }
        float2 a01 = upk2(sA01), a23 = upk2(sA23);
        float2 b01 = upk2(sB01), b23 = upk2(sB23);
        float eA0 = ex2f(a01.x), eA1 = ex2f(a01.y), eA2 = ex2f(a23.x), eA3 = ex2f(a23.y);
        float eB0 = ex2f(b01.x), eB1 = ex2f(b01.y), eB2 = ex2f(b23.x), eB3 = ex2f(b23.y);
        seA += (eA0 + eA1) + (eA2 + eA3);
        seB += (eB0 + eB1) + (eB2 + eB3);
        ull eA[4] = { pk2(eA0, eA0), pk2(eA1, eA1), pk2(eA2, eA2), pk2(eA3, eA3) };
        ull eB[4] = { pk2(eB0, eB0), pk2(eB1, eB1), pk2(eB2, eB2), pk2(eB3, eB3) };

        const ulonglong2* gq = (const ulonglong2*)(g2s + (size_t)q * 4 * (CG / 2));
#pragma unroll
        for (int d = 0; d < 4; d++) {
#pragma unroll
            for (int p = 0; p < CG / 4; p++) {
                ulonglong2 gv = gq[d * (CG / 4) + p];
                accA[2 * p]     = fma2(eA[d], gv.x, accA[2 * p]);
                accA[2 * p + 1] = fma2(eA[d], gv.y, accA[2 * p + 1]);
                accB[2 * p]     = fma2(eB[d], gv.x, accB[2 * p]);
                accB[2 * p + 1] = fma2(eB[d], gv.y, accB[2 * p + 1]);
            }
        }
    }

    float invA = 1.0f / seA;
    float invB = 1.0f / seB;
    ull invA2 = pk2(invA, invA), invB2 = pk2(invB, invB);
    ull rpA[CG / 2], rpB[CG / 2];
#pragma unroll
    for (int p = 0; p < CG / 2; p++) {
        rpA[p] = mul2(accA[p], invA2);
        rpB[p] = mul2(accB[p], invB2);
    }

    float gamma = *gammap;
    const float* xp = x + ((size_t)n * CH) * LL + l0;
    float* op = out + ((size_t)n * CH) * LL + l0;
    const ulonglong2* w2 = (const ulonglong2*)wos;    // [CH][CG/4]

#pragma unroll 4
    for (int oc = 0; oc < CH; oc++) {
        ull sA = 0ull, sB = 0ull;
#pragma unroll
        for (int p = 0; p < CG / 4; p++) {
            ulonglong2 wv = w2[oc * (CG / 4) + p];
            sA = fma2(rpA[2 * p], wv.x, sA);
            sA = fma2(rpA[2 * p + 1], wv.y, sA);
            sB = fma2(rpB[2 * p], wv.x, sB);
            sB = fma2(rpB[2 * p + 1], wv.y, sB);
        }
        float2 fa = upk2(sA), fb = upk2(sB);
        float2 xv = *(const float2*)(xp + (size_t)oc * LL);
        float2 ov;
        ov.x = fmaf(gamma, fa.x + fa.y, xv.x);
        ov.y = fmaf(gamma, fb.x + fb.y, xv.y);
        *(float2*)(op + (size_t)oc * LL) = ov;
    }
}

// ---------------------------------------------------------------------------
extern "C" void kernel_launch(void* const* d_in, const int* in_sizes, int n_in,
                              void* d_out, int out_size) {
    const float* x       = (const float*)d_in[0];
    const float* w_theta = (const float*)d_in[1];
    const float* w_phi   = (const float*)d_in[2];
    const float* w_g     = (const float*)d_in[3];
    const float* w_o     = (const float*)d_in[4];
    const float* gammap  = (const float*)d_in[5];
    float* out = (float*)d_out;

    const int smem_bytes = (CK * DD + DD * CG + CH * CG) * (int)sizeof(float); // 172032
    cudaFuncSetAttribute(attn_kernel, cudaFuncAttributeMaxDynamicSharedMemorySize,
                         smem_bytes);

    proj_theta_kernel<<<NB * LL / 512, 256>>>(x, w_theta);
    proj_pool_kernel<<<NB * DD / 256, 256>>>(x, w_phi, w_g);
    dim3 grid(LL / 512, NB);
    attn_kernel<<<grid, 256, smem_bytes>>>(x, w_o, gammap, out);
}

// round 5
// speedup vs baseline: 2.1284x; 1.5668x over previous
#include <cuda_runtime.h>
#include <cuda_bf16.h>
#include <cstdint>

// Problem constants
#define NB 16
#define CH 64
#define LL 4096   // H*W
#define DD 1024   // pooled locations
#define CK 8      // C>>3 (theta/phi channels)
#define CG 32     // C>>1 (g channels)

typedef unsigned long long ull;

// Scratch (device globals). Fragment-gather layouts:
//   phi_p[n][k][s][qf] = float4 {phi[d0],phi[d0+1],phi[d0+8],phi[d0+9]}, d0=16s+2qf
//   g_p  [n][j][s][qf] = bf16x4 (same d pattern)
__device__ __align__(16) float g_theta[NB * LL * CK];            // 8 MB
__device__ __align__(16) float g_phip[NB * CK * 256 * 4];        // 512 KB
__device__ __align__(16) __nv_bfloat16 g_gp[NB * CG * 256 * 4];  // 1 MB

__device__ __forceinline__ ull pk2(float a, float b) {
    ull r; asm("mov.b64 %0, {%1, %2};" : "=l"(r) : "f"(a), "f"(b)); return r;
}
__device__ __forceinline__ float2 upk2(ull v) {
    float2 r; asm("mov.b64 {%0, %1}, %2;" : "=f"(r.x), "=f"(r.y) : "l"(v)); return r;
}
__device__ __forceinline__ ull fma2(ull a, ull b, ull c) {
    ull d; asm("fma.rn.f32x2 %0, %1, %2, %3;" : "=l"(d) : "l"(a), "l"(b), "l"(c)); return d;
}
__device__ __forceinline__ float ex2f(float x) {
    float r; asm("ex2.approx.ftz.f32 %0, %1;" : "=f"(r) : "f"(x)); return r;
}
__device__ __forceinline__ uint32_t pbf2(float lo, float hi) {
    __nv_bfloat162 h = __floats2bfloat162_rn(lo, hi);   // .x = lo, .y = hi
    uint32_t u; *(__nv_bfloat162*)&u = h; return u;
}
// m16n8k16 row.col bf16 -> f32
__device__ __forceinline__ void mma16816(float* c, uint32_t a0, uint32_t a1,
                                         uint32_t a2, uint32_t a3,
                                         uint32_t b0, uint32_t b1) {
    asm volatile(
        "mma.sync.aligned.m16n8k16.row.col.f32.bf16.bf16.f32 "
        "{%0,%1,%2,%3}, {%4,%5,%6,%7}, {%8,%9}, {%0,%1,%2,%3};"
        : "+f"(c[0]), "+f"(c[1]), "+f"(c[2]), "+f"(c[3])
        : "r"(a0), "r"(a1), "r"(a2), "r"(a3), "r"(b0), "r"(b1));
}

// ---------------------------------------------------------------------------
// Fused projection kernel: one pass over x computes theta (log2e-scaled) and
// pooled phi / g in fragment-gather layouts.
// 256 CTAs x 256 threads; one thread per location; 2x2 pool via quad shfl.
// ---------------------------------------------------------------------------
__global__ void __launch_bounds__(256) proj_fused_kernel(
        const float* __restrict__ x, const float* __restrict__ w_theta,
        const float* __restrict__ w_phi, const float* __restrict__ w_g) {
    // weights packed over output-channel pairs: w2[c*P + kp] = {w[2kp][c], w[2kp+1][c]}
    __shared__ ull wt2[CH * 4];    // theta (x log2e)
    __shared__ ull wp2[CH * 4];    // phi
    __shared__ ull wg2[CH * 16];   // g
    int tid = threadIdx.x;
    for (int i = tid; i < CH * 4; i += 256) {
        int kp = i & 3, c = i >> 2;
        wt2[i] = pk2(w_theta[(2 * kp) * CH + c] * 1.4426950408889634f,
                     w_theta[(2 * kp + 1) * CH + c] * 1.4426950408889634f);
        wp2[i] = pk2(w_phi[(2 * kp) * CH + c], w_phi[(2 * kp + 1) * CH + c]);
    }
    for (int i = tid; i < CH * 16; i += 256) {
        int jp = i & 15, c = i >> 4;
        wg2[i] = pk2(w_g[(2 * jp) * CH + c], w_g[(2 * jp + 1) * CH + c]);
    }
    __syncthreads();

    int bid = blockIdx.x;
    int n = bid >> 4, yt = bid & 15;
    int b0 = tid & 1, b1 = (tid >> 1) & 1;
    int xpair = (tid >> 2) & 31;
    int yp = tid >> 7;                 // 0..1
    int y = yt * 4 + yp * 2 + b1;
    int xc = xpair * 2 + b0;
    int l = y * 64 + xc;

    const float* xp = x + ((size_t)n * CH) * LL + l;

    ull at[4], ap[4], ag[16];
#pragma unroll
    for (int i = 0; i < 4; i++) { at[i] = 0ull; ap[i] = 0ull; }
#pragma unroll
    for (int i = 0; i < 16; i++) ag[i] = 0ull;

#pragma unroll 8
    for (int c = 0; c < CH; c++) {
        float xv = xp[(size_t)c * LL];
        ull vd = pk2(xv, xv);
#pragma unroll
        for (int kp = 0; kp < 4; kp++) at[kp] = fma2(wt2[c * 4 + kp], vd, at[kp]);
#pragma unroll
        for (int kp = 0; kp < 4; kp++) ap[kp] = fma2(wp2[c * 4 + kp], vd, ap[kp]);
#pragma unroll
        for (int jp = 0; jp < 16; jp++) ag[jp] = fma2(wg2[c * 16 + jp], vd, ag[jp]);
    }

    // theta out
    {
        float2 t0 = upk2(at[0]), t1 = upk2(at[1]), t2 = upk2(at[2]), t3 = upk2(at[3]);
        float4* tp = (float4*)(g_theta + ((size_t)n * LL + l) * CK);
        tp[0] = make_float4(t0.x, t0.y, t1.x, t1.y);
        tp[1] = make_float4(t2.x, t2.y, t3.x, t3.y);
    }

    // 2x2 max-pool via quad shuffle
    float phv[CK], gv[CG];
#pragma unroll
    for (int kp = 0; kp < 4; kp++) {
        float2 v = upk2(ap[kp]); phv[2 * kp] = v.x; phv[2 * kp + 1] = v.y;
    }
#pragma unroll
    for (int jp = 0; jp < 16; jp++) {
        float2 v = upk2(ag[jp]); gv[2 * jp] = v.x; gv[2 * jp + 1] = v.y;
    }
#pragma unroll
    for (int k = 0; k < CK; k++) {
        float v = phv[k];
        v = fmaxf(v, __shfl_xor_sync(0xffffffffu, v, 1));
        v = fmaxf(v, __shfl_xor_sync(0xffffffffu, v, 2));
        phv[k] = v;
    }
#pragma unroll
    for (int j = 0; j < CG; j++) {
        float v = gv[j];
        v = fmaxf(v, __shfl_xor_sync(0xffffffffu, v, 1));
        v = fmaxf(v, __shfl_xor_sync(0xffffffffu, v, 2));
        gv[j] = v;
    }

    if ((tid & 3) == 0) {
        int d = (yt * 2 + yp) * 32 + xpair;   // pooled index
        int s = d >> 4;
        int u = (xpair >> 3) & 1;
        int qf = (xpair & 7) >> 1;
        int rb = xpair & 1;
        int elem = u * 2 + rb;
        float* pdst = g_phip + (size_t)n * 8192;
#pragma unroll
        for (int k = 0; k < CK; k++)
            pdst[(k * 256 + s * 4 + qf) * 4 + elem] = phv[k];
        __nv_bfloat16* gdst = g_gp + (size_t)n * 32768;
#pragma unroll
        for (int j = 0; j < CG; j++)
            gdst[(j * 256 + s * 4 + qf) * 4 + elem] = __float2bfloat16(gv[j]);
    }
}

// ---------------------------------------------------------------------------
// Attention kernel: HMMA flash. Grid (16 L-tiles, 16 n) x 512 threads.
// Warp w owns rows w*16..w*16+15 of a 256-location tile; P computed in
// A-fragment layout, accumulated by mma.sync into D[256,32], epilogue scalar.
// ---------------------------------------------------------------------------
#define SM_PHI 0
#define SM_G   32768
#define SM_WO  98816                         // 32768 + 32*258*8 = 98816
#define SM_AG  107008                        // + 8192
#define SMEM_SZ 143872                       // + 256*36*4 = 36864

__global__ void __launch_bounds__(512, 1) attn_kernel(
        const float* __restrict__ x, const float* __restrict__ w_o,
        const float* __restrict__ gammap, float* __restrict__ out) {
    extern __shared__ char smem[];
    float4* phs = (float4*)(smem + SM_PHI);      // [k*256 + s*4 + q]
    ull*    gsh = (ull*)(smem + SM_G);           // [j*258 + s*4 + q] (padded)
    float*  wos = (float*)(smem + SM_WO);
    float*  ag  = (float*)(smem + SM_AG);        // [256][36]

    int tid = threadIdx.x;
    int n = blockIdx.y;
    int l0 = blockIdx.x * 256;

    // Cooperative fills
    {
        const float4* s1 = (const float4*)(g_phip + (size_t)n * 8192);
        for (int i = tid; i < 2048; i += 512) phs[i] = s1[i];
        const ull* s2 = (const ull*)(g_gp + (size_t)n * 32768);
        for (int i = tid; i < 8192; i += 512) {
            int j = i >> 8;
            gsh[j * 258 + (i & 255)] = s2[i];
        }
        const float4* s3 = (const float4*)w_o;
        float4* d3 = (float4*)wos;
        for (int i = tid; i < 512; i += 512) d3[i] = s3[i];
    }

    int warp = tid >> 5, lane = tid & 31;
    int gr = lane >> 2, q = lane & 3;
    int rA = warp * 16 + gr;          // tile-local rows
    int rB = rA + 8;

    // theta as duplicated f32x2 pairs (global read; independent of smem fill)
    ull tkA[CK], tkB[CK];
    {
        const float4* ta = (const float4*)(g_theta + ((size_t)n * LL + l0 + rA) * CK);
        const float4* tb = (const float4*)(g_theta + ((size_t)n * LL + l0 + rB) * CK);
        float4 a0 = ta[0], a1 = ta[1], b0 = tb[0], b1 = tb[1];
        tkA[0] = pk2(a0.x, a0.x); tkA[1] = pk2(a0.y, a0.y);
        tkA[2] = pk2(a0.z, a0.z); tkA[3] = pk2(a0.w, a0.w);
        tkA[4] = pk2(a1.x, a1.x); tkA[5] = pk2(a1.y, a1.y);
        tkA[6] = pk2(a1.z, a1.z); tkA[7] = pk2(a1.w, a1.w);
        tkB[0] = pk2(b0.x, b0.x); tkB[1] = pk2(b0.y, b0.y);
        tkB[2] = pk2(b0.z, b0.z); tkB[3] = pk2(b0.w, b0.w);
        tkB[4] = pk2(b1.x, b1.x); tkB[5] = pk2(b1.y, b1.y);
        tkB[6] = pk2(b1.z, b1.z); tkB[7] = pk2(b1.w, b1.w);
    }
    __syncthreads();

    float c0[4], c1[4], c2[4], c3[4];
#pragma unroll
    for (int i = 0; i < 4; i++) { c0[i] = 0.f; c1[i] = 0.f; c2[i] = 0.f; c3[i] = 0.f; }
    float seA = 0.f, seB = 0.f;

#pragma unroll 2
    for (int s = 0; s < 64; s++) {
        int base = s * 4 + q;
        ull lgA01 = 0ull, lgA89 = 0ull, lgB01 = 0ull, lgB89 = 0ull;
#pragma unroll
        for (int k = 0; k < CK; k++) {
            float4 pv4 = phs[k * 256 + base];
            ull pv01 = pk2(pv4.x, pv4.y);
            ull pv89 = pk2(pv4.z, pv4.w);
            lgA01 = fma2(tkA[k], pv01, lgA01);
            lgA89 = fma2(tkA[k], pv89, lgA89);
            lgB01 = fma2(tkB[k], pv01, lgB01);
            lgB89 = fma2(tkB[k], pv89, lgB89);
        }
        float2 fa01 = upk2(lgA01), fa89 = upk2(lgA89);
        float2 fb01 = upk2(lgB01), fb89 = upk2(lgB89);
        float eA0 = ex2f(fa01.x), eA1 = ex2f(fa01.y);
        float eA8 = ex2f(fa89.x), eA9 = ex2f(fa89.y);
        float eB0 = ex2f(fb01.x), eB1 = ex2f(fb01.y);
        float eB8 = ex2f(fb89.x), eB9 = ex2f(fb89.y);
        seA += (eA0 + eA1) + (eA8 + eA9);
        seB += (eB0 + eB1) + (eB8 + eB9);
        uint32_t a0 = pbf2(eA0, eA1), a1 = pbf2(eB0, eB1);
        uint32_t a2 = pbf2(eA8, eA9), a3 = pbf2(eB8, eB9);

        ull gv0 = gsh[(gr) * 258 + base];
        ull gv1 = gsh[(gr + 8) * 258 + base];
        ull gv2 = gsh[(gr + 16) * 258 + base];
        ull gv3 = gsh[(gr + 24) * 258 + base];
        mma16816(c0, a0, a1, a2, a3, (uint32_t)gv0, (uint32_t)(gv0 >> 32));
        mma16816(c1, a0, a1, a2, a3, (uint32_t)gv1, (uint32_t)(gv1 >> 32));
        mma16816(c2, a0, a1, a2, a3, (uint32_t)gv2, (uint32_t)(gv2 >> 32));
        mma16816(c3, a0, a1, a2, a3, (uint32_t)gv3, (uint32_t)(gv3 >> 32));
    }

    // row sums across the quad
    seA += __shfl_xor_sync(0xffffffffu, seA, 1);
    seA += __shfl_xor_sync(0xffffffffu, seA, 2);
    seB += __shfl_xor_sync(0xffffffffu, seB, 1);
    seB += __shfl_xor_sync(0xffffffffu, seB, 2);
    float invA = 1.0f / seA, invB = 1.0f / seB;

    // stash normalized attn_g to smem: ag[row][j]
    {
        int col = 2 * q;
        *(float2*)(ag + rA * 36 + col)      = make_float2(c0[0] * invA, c0[1] * invA);
        *(float2*)(ag + rB * 36 + col)      = make_float2(c0[2] * invB, c0[3] * invB);
        *(float2*)(ag + rA * 36 + col + 8)  = make_float2(c1[0] * invA, c1[1] * invA);
        *(float2*)(ag + rB * 36 + col + 8)  = make_float2(c1[2] * invB, c1[3] * invB);
        *(float2*)(ag + rA * 36 + col + 16) = make_float2(c2[0] * invA, c2[1] * invA);
        *(float2*)(ag + rB * 36 + col + 16) = make_float2(c2[2] * invB, c2[3] * invB);
        *(float2*)(ag + rA * 36 + col + 24) = make_float2(c3[0] * invA, c3[1] * invA);
        *(float2*)(ag + rB * 36 + col + 24) = make_float2(c3[2] * invB, c3[3] * invB);
    }
    __syncthreads();

    // Epilogue: thread (r = tid>>1, h = tid&1) -> out[h*32 .. h*32+31][l0+r]
    int r = tid >> 1, h = tid & 1;
    ull rp[CG / 2];
    {
        const ulonglong2* apt = (const ulonglong2*)(ag + (size_t)r * 36);
#pragma unroll
        for (int p = 0; p < CG / 4; p++) {
            ulonglong2 v = apt[p];
            rp[2 * p] = v.x; rp[2 * p + 1] = v.y;
        }
    }
    float gamma = *gammap;
    const float* xp = x + ((size_t)n * CH + h * 32) * LL + l0 + r;
    float* op = out + ((size_t)n * CH + h * 32) * LL + l0 + r;
    const ulonglong2* w2 = (const ulonglong2*)wos;

#pragma unroll 4
    for (int i = 0; i < 32; i++) {
        int oc = h * 32 + i;
        ull s2 = 0ull;
#pragma unroll
        for (int p = 0; p < CG / 4; p++) {
            ulonglong2 wv = w2[oc * (CG / 4) + p];
            s2 = fma2(rp[2 * p], wv.x, s2);
            s2 = fma2(rp[2 * p + 1], wv.y, s2);
        }
        float2 sf = upk2(s2);
        op[(size_t)i * LL] = fmaf(gamma, sf.x + sf.y, xp[(size_t)i * LL]);
    }
}

// ---------------------------------------------------------------------------
extern "C" void kernel_launch(void* const* d_in, const int* in_sizes, int n_in,
                              void* d_out, int out_size) {
    const float* x       = (const float*)d_in[0];
    const float* w_theta = (const float*)d_in[1];
    const float* w_phi   = (const float*)d_in[2];
    const float* w_g     = (const float*)d_in[3];
    const float* w_o     = (const float*)d_in[4];
    const float* gammap  = (const float*)d_in[5];
    float* out = (float*)d_out;

    cudaFuncSetAttribute(attn_kernel, cudaFuncAttributeMaxDynamicSharedMemorySize,
                         SMEM_SZ);

    proj_fused_kernel<<<256, 256>>>(x, w_theta, w_phi, w_g);
    dim3 grid(LL / 256, NB);
    attn_kernel<<<grid, 512, SMEM_SZ>>>(x, w_o, gammap, out);
}

// round 6
// speedup vs baseline: 3.3803x; 1.5882x over previous
#include <cuda_runtime.h>
#include <cuda_fp16.h>
#include <cstdint>

// Problem constants
#define NB 16
#define CH 64
#define LL 4096   // H*W
#define DD 1024   // pooled locations
#define CK 8      // C>>3 (theta/phi channels)
#define CG 32     // C>>1 (g channels)

typedef unsigned long long ull;

// Scratch (device globals):
//  g_thetaH[n][l][q]   u32 = f16x2 {theta[2q], theta[2q+1]}, pre-scaled by log2(e)
//  g_phiH  [n][d][q]   u32 = f16x2 {phi[2q][d], phi[2q+1][d]}
//  g_gH    [n][j][s*4+q][elem]  f16, elem -> d = 16s + {2q,2q+1,2q+8,2q+9}
__device__ __align__(16) uint32_t g_thetaH[NB * LL * 4];   // 4 MB
__device__ __align__(16) uint32_t g_phiH[NB * DD * 4];     // 256 KB
__device__ __align__(16) __half   g_gH[NB * CG * 1024];    // 1 MB

__device__ __forceinline__ ull pk2(float a, float b) {
    ull r; asm("mov.b64 %0, {%1, %2};" : "=l"(r) : "f"(a), "f"(b)); return r;
}
__device__ __forceinline__ float2 upk2(ull v) {
    float2 r; asm("mov.b64 {%0, %1}, %2;" : "=f"(r.x), "=f"(r.y) : "l"(v)); return r;
}
__device__ __forceinline__ ull fma2(ull a, ull b, ull c) {
    ull d; asm("fma.rn.f32x2 %0, %1, %2, %3;" : "=l"(d) : "l"(a), "l"(b), "l"(c)); return d;
}
// pack two f32 -> f16x2 (lo, hi)
__device__ __forceinline__ uint32_t pack_h2(float lo, float hi) {
    uint32_t r; asm("cvt.rn.f16x2.f32 %0, %1, %2;" : "=r"(r) : "f"(hi), "f"(lo)); return r;
}
__device__ __forceinline__ uint32_t ex2h2(uint32_t h) {
    uint32_t r; asm("ex2.approx.f16x2 %0, %1;" : "=r"(r) : "r"(h)); return r;
}
__device__ __forceinline__ __half2 u2h(uint32_t u) { return *(__half2*)&u; }

// MMA1: m16n8k8 f16, C = 0
__device__ __forceinline__ void mma_k8(float* d, uint32_t a0, uint32_t a1, uint32_t b0) {
    asm volatile(
        "mma.sync.aligned.m16n8k8.row.col.f32.f16.f16.f32 "
        "{%0,%1,%2,%3}, {%4,%5}, {%6}, {%7,%8,%9,%10};"
        : "=f"(d[0]), "=f"(d[1]), "=f"(d[2]), "=f"(d[3])
        : "r"(a0), "r"(a1), "r"(b0),
          "f"(0.f), "f"(0.f), "f"(0.f), "f"(0.f));
}
// MMA2: m16n8k16 f16, accumulate
__device__ __forceinline__ void mma_k16(float* c, uint32_t a0, uint32_t a1,
                                        uint32_t a2, uint32_t a3,
                                        uint32_t b0, uint32_t b1) {
    asm volatile(
        "mma.sync.aligned.m16n8k16.row.col.f32.f16.f16.f32 "
        "{%0,%1,%2,%3}, {%4,%5,%6,%7}, {%8,%9}, {%0,%1,%2,%3};"
        : "+f"(c[0]), "+f"(c[1]), "+f"(c[2]), "+f"(c[3])
        : "r"(a0), "r"(a1), "r"(a2), "r"(a3), "r"(b0), "r"(b1));
}

// ---------------------------------------------------------------------------
// Fused projection kernel: theta (f16x2 pairs, log2e-scaled), pooled phi
// (f16x2 pairs) and pooled g (f16 fragment-gather layout).
// 256 CTAs x 256 threads; one thread per location; 2x2 pool via quad shfl.
// ---------------------------------------------------------------------------
__global__ void __launch_bounds__(256) proj_fused_kernel(
        const float* __restrict__ x, const float* __restrict__ w_theta,
        const float* __restrict__ w_phi, const float* __restrict__ w_g) {
    __shared__ ull wt2[CH * 4];    // theta (x log2e), channel pairs
    __shared__ ull wp2[CH * 4];    // phi
    __shared__ ull wg2[CH * 16];   // g
    int tid = threadIdx.x;
    for (int i = tid; i < CH * 4; i += 256) {
        int kp = i & 3, c = i >> 2;
        wt2[i] = pk2(w_theta[(2 * kp) * CH + c] * 1.4426950408889634f,
                     w_theta[(2 * kp + 1) * CH + c] * 1.4426950408889634f);
        wp2[i] = pk2(w_phi[(2 * kp) * CH + c], w_phi[(2 * kp + 1) * CH + c]);
    }
    for (int i = tid; i < CH * 16; i += 256) {
        int jp = i & 15, c = i >> 4;
        wg2[i] = pk2(w_g[(2 * jp) * CH + c], w_g[(2 * jp + 1) * CH + c]);
    }
    __syncthreads();

    int bid = blockIdx.x;
    int n = bid >> 4, yt = bid & 15;
    int b0 = tid & 1, b1 = (tid >> 1) & 1;
    int xpair = (tid >> 2) & 31;
    int yp = tid >> 7;
    int y = yt * 4 + yp * 2 + b1;
    int xc = xpair * 2 + b0;
    int l = y * 64 + xc;

    const float* xp = x + ((size_t)n * CH) * LL + l;

    ull at[4], ap[4], ag[16];
#pragma unroll
    for (int i = 0; i < 4; i++) { at[i] = 0ull; ap[i] = 0ull; }
#pragma unroll
    for (int i = 0; i < 16; i++) ag[i] = 0ull;

#pragma unroll 8
    for (int c = 0; c < CH; c++) {
        float xv = xp[(size_t)c * LL];
        ull vd = pk2(xv, xv);
#pragma unroll
        for (int kp = 0; kp < 4; kp++) at[kp] = fma2(wt2[c * 4 + kp], vd, at[kp]);
#pragma unroll
        for (int kp = 0; kp < 4; kp++) ap[kp] = fma2(wp2[c * 4 + kp], vd, ap[kp]);
#pragma unroll
        for (int jp = 0; jp < 16; jp++) ag[jp] = fma2(wg2[c * 16 + jp], vd, ag[jp]);
    }

    // theta out (f16x2 pairs)
    {
        float2 t0 = upk2(at[0]), t1 = upk2(at[1]), t2 = upk2(at[2]), t3 = upk2(at[3]);
        uint4 tq;
        tq.x = pack_h2(t0.x, t0.y);
        tq.y = pack_h2(t1.x, t1.y);
        tq.z = pack_h2(t2.x, t2.y);
        tq.w = pack_h2(t3.x, t3.y);
        *(uint4*)(g_thetaH + ((size_t)n * LL + l) * 4) = tq;
    }

    // 2x2 max-pool via quad shuffle
    float phv[CK], gv[CG];
#pragma unroll
    for (int kp = 0; kp < 4; kp++) {
        float2 v = upk2(ap[kp]); phv[2 * kp] = v.x; phv[2 * kp + 1] = v.y;
    }
#pragma unroll
    for (int jp = 0; jp < 16; jp++) {
        float2 v = upk2(ag[jp]); gv[2 * jp] = v.x; gv[2 * jp + 1] = v.y;
    }
#pragma unroll
    for (int k = 0; k < CK; k++) {
        float v = phv[k];
        v = fmaxf(v, __shfl_xor_sync(0xffffffffu, v, 1));
        v = fmaxf(v, __shfl_xor_sync(0xffffffffu, v, 2));
        phv[k] = v;
    }
#pragma unroll
    for (int j = 0; j < CG; j++) {
        float v = gv[j];
        v = fmaxf(v, __shfl_xor_sync(0xffffffffu, v, 1));
        v = fmaxf(v, __shfl_xor_sync(0xffffffffu, v, 2));
        gv[j] = v;
    }

    if ((tid & 3) == 0) {
        int d = (yt * 2 + yp) * 32 + xpair;   // pooled index
        // phi: f16x2 k-pairs at [n][d][q]
        uint4 pq;
        pq.x = pack_h2(phv[0], phv[1]);
        pq.y = pack_h2(phv[2], phv[3]);
        pq.z = pack_h2(phv[4], phv[5]);
        pq.w = pack_h2(phv[6], phv[7]);
        *(uint4*)(g_phiH + ((size_t)n * DD + d) * 4) = pq;

        // g: fragment-gather f16
        int s = d >> 4;
        int u = (xpair >> 3) & 1;
        int qf = (xpair & 7) >> 1;
        int rb = xpair & 1;
        int elem = u * 2 + rb;
        __half* gdst = g_gH + (size_t)n * CG * 1024;
#pragma unroll
        for (int j = 0; j < CG; j++)
            gdst[(j * 256 + s * 4 + qf) * 4 + elem] = __float2half_rn(gv[j]);
    }
}

// ---------------------------------------------------------------------------
// Attention kernel: full tensor-core flash (MMA1 logits -> exp -> MMA2).
// Grid (16 L-tiles, 16 n) x 512 threads, 2 CTAs/SM (90.6 KB smem).
// ---------------------------------------------------------------------------
#define SM_PHI 0
#define SM_G   16384
#define SM_WO  82432
#define SMEM_SZ 90624

__global__ void __launch_bounds__(512, 2) attn_kernel(
        const float* __restrict__ x, const float* __restrict__ w_o,
        const float* __restrict__ gammap, float* __restrict__ out) {
    extern __shared__ char smem[];
    uint32_t* phs = (uint32_t*)(smem + SM_PHI);   // [d*4 + q] f16x2
    ull*      gsh = (ull*)(smem + SM_G);          // [j*258 + s*4 + q] (padded rows)
    float*    wos = (float*)(smem + SM_WO);
    float*    ag  = (float*)smem;                 // overlay after mainloop: [256][36]

    int tid = threadIdx.x;
    int n = blockIdx.y;
    int l0 = blockIdx.x * 256;

    // Cooperative fills
    {
        const uint4* s1 = (const uint4*)(g_phiH + (size_t)n * DD * 4);
        uint4* d1 = (uint4*)phs;
        for (int i = tid; i < 1024; i += 512) d1[i] = s1[i];
        const ull* s2 = (const ull*)(g_gH + (size_t)n * CG * 1024);
        for (int i = tid; i < 8192; i += 512) {
            int j = i >> 8;
            gsh[j * 258 + (i & 255)] = s2[i];
        }
        const float4* s3 = (const float4*)w_o;
        float4* d3 = (float4*)wos;
        for (int i = tid; i < 512; i += 512) d3[i] = s3[i];
    }

    int warp = tid >> 5, lane = tid & 31;
    int gr = lane >> 2, q = lane & 3;
    int rA = warp * 16 + gr;
    int rB = rA + 8;

    // theta A-fragment (f16x2 pairs {2q,2q+1}), loop-invariant
    uint32_t tA = g_thetaH[((size_t)n * LL + l0 + rA) * 4 + q];
    uint32_t tB = g_thetaH[((size_t)n * LL + l0 + rB) * 4 + q];
    __syncthreads();

    float c0[4], c1[4], c2[4], c3[4];
#pragma unroll
    for (int i = 0; i < 4; i++) { c0[i] = 0.f; c1[i] = 0.f; c2[i] = 0.f; c3[i] = 0.f; }
    float seA = 0.f, seB = 0.f;

#pragma unroll 2
    for (int s = 0; s < 64; s++) {
        int base = s * 4 + q;
        // MMA1: logits for d-blocks u=0,1 (cols 16s+u*8+0..7)
        uint32_t pv0 = phs[(16 * s + gr) * 4 + q];
        uint32_t pv1 = phs[(16 * s + 8 + gr) * 4 + q];
        float s0[4], s1v[4];
        mma_k8(s0, tA, tB, pv0);
        mma_k8(s1v, tA, tB, pv1);
        // exp (f16x2): fragments line up exactly with MMA2 A layout
        uint32_t a0 = ex2h2(pack_h2(s0[0], s0[1]));    // row gr,  k 2q,2q+1
        uint32_t a1 = ex2h2(pack_h2(s0[2], s0[3]));    // row gr+8
        uint32_t a2 = ex2h2(pack_h2(s1v[0], s1v[1]));  // row gr,  k 2q+8,2q+9
        uint32_t a3 = ex2h2(pack_h2(s1v[2], s1v[3]));  // row gr+8
        // row partial sums
        float2 fA = __half22float2(__hadd2(u2h(a0), u2h(a2)));
        float2 fB = __half22float2(__hadd2(u2h(a1), u2h(a3)));
        seA += fA.x + fA.y;
        seB += fB.x + fB.y;
        // MMA2: accumulate attn_g over 4 g-channel blocks
        ull gv0 = gsh[gr * 258 + base];
        ull gv1 = gsh[(gr + 8) * 258 + base];
        ull gv2 = gsh[(gr + 16) * 258 + base];
        ull gv3 = gsh[(gr + 24) * 258 + base];
        mma_k16(c0, a0, a1, a2, a3, (uint32_t)gv0, (uint32_t)(gv0 >> 32));
        mma_k16(c1, a0, a1, a2, a3, (uint32_t)gv1, (uint32_t)(gv1 >> 32));
        mma_k16(c2, a0, a1, a2, a3, (uint32_t)gv2, (uint32_t)(gv2 >> 32));
        mma_k16(c3, a0, a1, a2, a3, (uint32_t)gv3, (uint32_t)(gv3 >> 32));
    }

    // row sums across the quad
    seA += __shfl_xor_sync(0xffffffffu, seA, 1);
    seA += __shfl_xor_sync(0xffffffffu, seA, 2);
    seB += __shfl_xor_sync(0xffffffffu, seB, 1);
    seB += __shfl_xor_sync(0xffffffffu, seB, 2);
    float invA = 1.0f / seA, invB = 1.0f / seB;

    __syncthreads();   // phi/g reads done; safe to overlay ag

    {
        int col = 2 * q;
        *(float2*)(ag + rA * 36 + col)      = make_float2(c0[0] * invA, c0[1] * invA);
        *(float2*)(ag + rB * 36 + col)      = make_float2(c0[2] * invB, c0[3] * invB);
        *(float2*)(ag + rA * 36 + col + 8)  = make_float2(c1[0] * invA, c1[1] * invA);
        *(float2*)(ag + rB * 36 + col + 8)  = make_float2(c1[2] * invB, c1[3] * invB);
        *(float2*)(ag + rA * 36 + col + 16) = make_float2(c2[0] * invA, c2[1] * invA);
        *(float2*)(ag + rB * 36 + col + 16) = make_float2(c2[2] * invB, c2[3] * invB);
        *(float2*)(ag + rA * 36 + col + 24) = make_float2(c3[0] * invA, c3[1] * invA);
        *(float2*)(ag + rB * 36 + col + 24) = make_float2(c3[2] * invB, c3[3] * invB);
    }
    __syncthreads();

    // Epilogue: thread (r = tid>>1, h = tid&1) -> out[h*32 .. +31][l0+r]
    int r = tid >> 1, h = tid & 1;
    ull rp[CG / 2];
    {
        const ulonglong2* apt = (const ulonglong2*)(ag + (size_t)r * 36);
#pragma unroll
        for (int p = 0; p < CG / 4; p++) {
            ulonglong2 v = apt[p];
            rp[2 * p] = v.x; rp[2 * p + 1] = v.y;
        }
    }
    float gamma = *gammap;
    const float* xp = x + ((size_t)n * CH + h * 32) * LL + l0 + r;
    float* op = out + ((size_t)n * CH + h * 32) * LL + l0 + r;
    const ulonglong2* w2 = (const ulonglong2*)wos;

#pragma unroll 4
    for (int i = 0; i < 32; i++) {
        int oc = h * 32 + i;
        ull s2 = 0ull;
#pragma unroll
        for (int p = 0; p < CG / 4; p++) {
            ulonglong2 wv = w2[oc * (CG / 4) + p];
            s2 = fma2(rp[2 * p], wv.x, s2);
            s2 = fma2(rp[2 * p + 1], wv.y, s2);
        }
        float2 sf = upk2(s2);
        op[(size_t)i * LL] = fmaf(gamma, sf.x + sf.y, xp[(size_t)i * LL]);
    }
}

// ---------------------------------------------------------------------------
extern "C" void kernel_launch(void* const* d_in, const int* in_sizes, int n_in,
                              void* d_out, int out_size) {
    const float* x       = (const float*)d_in[0];
    const float* w_theta = (const float*)d_in[1];
    const float* w_phi   = (const float*)d_in[2];
    const float* w_g     = (const float*)d_in[3];
    const float* w_o     = (const float*)d_in[4];
    const float* gammap  = (const float*)d_in[5];
    float* out = (float*)d_out;

    cudaFuncSetAttribute(attn_kernel, cudaFuncAttributeMaxDynamicSharedMemorySize,
                         SMEM_SZ);

    proj_fused_kernel<<<256, 256>>>(x, w_theta, w_phi, w_g);
    dim3 grid(LL / 256, NB);
    attn_kernel<<<grid, 512, SMEM_SZ>>>(x, w_o, gammap, out);
}

// round 7
// speedup vs baseline: 3.5488x; 1.0498x over previous
#include <cuda_runtime.h>
#include <cuda_fp16.h>
#include <cstdint>

// Problem constants
#define NB 16
#define CH 64
#define LL 4096   // H*W
#define DD 1024   // pooled locations
#define CK 8      // C>>3 (theta/phi channels)
#define CG 32     // C>>1 (g channels)

typedef unsigned long long ull;

// Scratch (device globals):
//  g_thetaH[n][l][q]  u32 = f16x2 {theta[2q], theta[2q+1]}, pre-scaled by log2(e)
//  g_phiP  [n][4096]  u32, phi in fused-B layout: idx = s*64 + gr*8 + q*2 + u
//                     holding f16x2 k-pair q of pooled col d = 16s + u*8 + gr
//  g_gH    [n][j][s*4+q][elem] f16, elem -> d = 16s + {2q,2q+1,2q+8,2q+9}
__device__ __align__(16) uint32_t g_thetaH[NB * LL * 4];   // 4 MB
__device__ __align__(16) uint32_t g_phiP[NB * 4096];       // 256 KB
__device__ __align__(16) __half   g_gH[NB * CG * 1024];    // 1 MB

__device__ __forceinline__ ull pk2(float a, float b) {
    ull r; asm("mov.b64 %0, {%1, %2};" : "=l"(r) : "f"(a), "f"(b)); return r;
}
__device__ __forceinline__ float2 upk2(ull v) {
    float2 r; asm("mov.b64 {%0, %1}, %2;" : "=f"(r.x), "=f"(r.y) : "l"(v)); return r;
}
__device__ __forceinline__ ull fma2(ull a, ull b, ull c) {
    ull d; asm("fma.rn.f32x2 %0, %1, %2, %3;" : "=l"(d) : "l"(a), "l"(b), "l"(c)); return d;
}
__device__ __forceinline__ uint32_t pack_h2(float lo, float hi) {
    uint32_t r; asm("cvt.rn.f16x2.f32 %0, %1, %2;" : "=r"(r) : "f"(hi), "f"(lo)); return r;
}
__device__ __forceinline__ uint32_t ex2h2(uint32_t h) {
    uint32_t r; asm("ex2.approx.f16x2 %0, %1;" : "=r"(r) : "r"(h)); return r;
}
__device__ __forceinline__ __half2 u2h(uint32_t u) { return *(__half2*)&u; }

// MMA1: m16n8k8 f16, C = 0
__device__ __forceinline__ void mma_k8(float* d, uint32_t a0, uint32_t a1, uint32_t b0) {
    asm volatile(
        "mma.sync.aligned.m16n8k8.row.col.f32.f16.f16.f32 "
        "{%0,%1,%2,%3}, {%4,%5}, {%6}, {%7,%8,%9,%10};"
        : "=f"(d[0]), "=f"(d[1]), "=f"(d[2]), "=f"(d[3])
        : "r"(a0), "r"(a1), "r"(b0),
          "f"(0.f), "f"(0.f), "f"(0.f), "f"(0.f));
}
// MMA2: m16n8k16 f16, accumulate
__device__ __forceinline__ void mma_k16(float* c, uint32_t a0, uint32_t a1,
                                        uint32_t a2, uint32_t a3,
                                        uint32_t b0, uint32_t b1) {
    asm volatile(
        "mma.sync.aligned.m16n8k16.row.col.f32.f16.f16.f32 "
        "{%0,%1,%2,%3}, {%4,%5,%6,%7}, {%8,%9}, {%0,%1,%2,%3};"
        : "+f"(c[0]), "+f"(c[1]), "+f"(c[2]), "+f"(c[3])
        : "r"(a0), "r"(a1), "r"(a2), "r"(a3), "r"(b0), "r"(b1));
}

// ---------------------------------------------------------------------------
// Fused projection kernel (as R6, phi written in fused-B global layout).
// ---------------------------------------------------------------------------
__global__ void __launch_bounds__(256) proj_fused_kernel(
        const float* __restrict__ x, const float* __restrict__ w_theta,
        const float* __restrict__ w_phi, const float* __restrict__ w_g) {
    __shared__ ull wt2[CH * 4];
    __shared__ ull wp2[CH * 4];
    __shared__ ull wg2[CH * 16];
    int tid = threadIdx.x;
    for (int i = tid; i < CH * 4; i += 256) {
        int kp = i & 3, c = i >> 2;
        wt2[i] = pk2(w_theta[(2 * kp) * CH + c] * 1.4426950408889634f,
                     w_theta[(2 * kp + 1) * CH + c] * 1.4426950408889634f);
        wp2[i] = pk2(w_phi[(2 * kp) * CH + c], w_phi[(2 * kp + 1) * CH + c]);
    }
    for (int i = tid; i < CH * 16; i += 256) {
        int jp = i & 15, c = i >> 4;
        wg2[i] = pk2(w_g[(2 * jp) * CH + c], w_g[(2 * jp + 1) * CH + c]);
    }
    __syncthreads();

    int bid = blockIdx.x;
    int n = bid >> 4, yt = bid & 15;
    int b0 = tid & 1, b1 = (tid >> 1) & 1;
    int xpair = (tid >> 2) & 31;
    int yp = tid >> 7;
    int y = yt * 4 + yp * 2 + b1;
    int xc = xpair * 2 + b0;
    int l = y * 64 + xc;

    const float* xp = x + ((size_t)n * CH) * LL + l;

    ull at[4], ap[4], ag[16];
#pragma unroll
    for (int i = 0; i < 4; i++) { at[i] = 0ull; ap[i] = 0ull; }
#pragma unroll
    for (int i = 0; i < 16; i++) ag[i] = 0ull;

#pragma unroll 8
    for (int c = 0; c < CH; c++) {
        float xv = xp[(size_t)c * LL];
        ull vd = pk2(xv, xv);
#pragma unroll
        for (int kp = 0; kp < 4; kp++) at[kp] = fma2(wt2[c * 4 + kp], vd, at[kp]);
#pragma unroll
        for (int kp = 0; kp < 4; kp++) ap[kp] = fma2(wp2[c * 4 + kp], vd, ap[kp]);
#pragma unroll
        for (int jp = 0; jp < 16; jp++) ag[jp] = fma2(wg2[c * 16 + jp], vd, ag[jp]);
    }

    // theta out
    {
        float2 t0 = upk2(at[0]), t1 = upk2(at[1]), t2 = upk2(at[2]), t3 = upk2(at[3]);
        uint4 tq;
        tq.x = pack_h2(t0.x, t0.y);
        tq.y = pack_h2(t1.x, t1.y);
        tq.z = pack_h2(t2.x, t2.y);
        tq.w = pack_h2(t3.x, t3.y);
        *(uint4*)(g_thetaH + ((size_t)n * LL + l) * 4) = tq;
    }

    // 2x2 max-pool via quad shuffle
    float phv[CK], gv[CG];
#pragma unroll
    for (int kp = 0; kp < 4; kp++) {
        float2 v = upk2(ap[kp]); phv[2 * kp] = v.x; phv[2 * kp + 1] = v.y;
    }
#pragma unroll
    for (int jp = 0; jp < 16; jp++) {
        float2 v = upk2(ag[jp]); gv[2 * jp] = v.x; gv[2 * jp + 1] = v.y;
    }
#pragma unroll
    for (int k = 0; k < CK; k++) {
        float v = phv[k];
        v = fmaxf(v, __shfl_xor_sync(0xffffffffu, v, 1));
        v = fmaxf(v, __shfl_xor_sync(0xffffffffu, v, 2));
        phv[k] = v;
    }
#pragma unroll
    for (int j = 0; j < CG; j++) {
        float v = gv[j];
        v = fmaxf(v, __shfl_xor_sync(0xffffffffu, v, 1));
        v = fmaxf(v, __shfl_xor_sync(0xffffffffu, v, 2));
        gv[j] = v;
    }

    if ((tid & 3) == 0) {
        int d = (yt * 2 + yp) * 32 + xpair;   // pooled index
        // phi -> fused-B layout: idx = s*64 + gr*8 + q*2 + u
        int s = d >> 4, gr = d & 7, u = (d >> 3) & 1;
        uint32_t* pdst = g_phiP + (size_t)n * 4096 + s * 64 + gr * 8 + u;
        pdst[0] = pack_h2(phv[0], phv[1]);
        pdst[2] = pack_h2(phv[2], phv[3]);
        pdst[4] = pack_h2(phv[4], phv[5]);
        pdst[6] = pack_h2(phv[6], phv[7]);

        // g: fragment-gather f16 (unchanged)
        int xu = (xpair >> 3) & 1;
        int qf = (xpair & 7) >> 1;
        int rb = xpair & 1;
        int elem = xu * 2 + rb;
        __half* gdst = g_gH + (size_t)n * CG * 1024;
#pragma unroll
        for (int j = 0; j < CG; j++)
            gdst[(j * 256 + s * 4 + qf) * 4 + elem] = __float2half_rn(gv[j]);
    }
}

// ---------------------------------------------------------------------------
// Attention kernel: pipelined tensor-core flash.
// Grid (16 L-tiles, 16 n) x 512 threads, 2 CTAs/SM.
// smem: phi 16KB | gA 32.5KB | gB 32.5KB | w_o 8KB = 91,136 B
//  gA[gr][sq] = ull2 {g-row gr, g-row gr+8},  stride 260 ull2/row (conflict-free)
//  gB same for rows gr+16 / gr+24.
// ---------------------------------------------------------------------------
#define SM_PHI 0
#define SM_GA  16384
#define SM_GB  49664
#define SM_WO  82944
#define SMEM_SZ 91136

__global__ void __launch_bounds__(512, 2) attn_kernel(
        const float* __restrict__ x, const float* __restrict__ w_o,
        const float* __restrict__ gammap, float* __restrict__ out) {
    extern __shared__ char smem[];
    float* wos = (float*)(smem + SM_WO);
    float* ag  = (float*)smem;                 // overlay after mainloop: [256][36]

    int tid = threadIdx.x;
    int n = blockIdx.y;
    int l0 = blockIdx.x * 256;

    // Cooperative fills
    {
        const uint4* s1 = (const uint4*)(g_phiP + (size_t)n * 4096);
        uint4* d1 = (uint4*)(smem + SM_PHI);
        for (int i = tid; i < 1024; i += 512) d1[i] = s1[i];
        // g remap: src ull idx i = j*256 + sq
        const ull* s2 = (const ull*)(g_gH + (size_t)n * CG * 1024);
        ull* gA = (ull*)(smem + SM_GA);
        ull* gB = (ull*)(smem + SM_GB);
        for (int i = tid; i < 8192; i += 512) {
            ull v = s2[i];
            int j = i >> 8, sq = i & 255;
            int gr = j & 7, half = (j >> 3) & 1;
            ull* arr = (j < 16) ? gA : gB;
            arr[(gr * 260 + sq) * 2 + half] = v;
        }
        const float4* s3 = (const float4*)w_o;
        float4* d3 = (float4*)wos;
        for (int i = tid; i < 512; i += 512) d3[i] = s3[i];
    }

    int warp = tid >> 5, lane = tid & 31;
    int gr = lane >> 2, q = lane & 3;
    int rA = warp * 16 + gr;
    int rB = rA + 8;

    uint32_t tA = g_thetaH[((size_t)n * LL + l0 + rA) * 4 + q];
    uint32_t tB = g_thetaH[((size_t)n * LL + l0 + rB) * 4 + q];
    __syncthreads();

    float c0[4], c1[4], c2[4], c3[4];
#pragma unroll
    for (int i = 0; i < 4; i++) { c0[i] = 0.f; c1[i] = 0.f; c2[i] = 0.f; c3[i] = 0.f; }
    float seA = 0.f, seB = 0.f;

    // mainloop pointers (advance per s: phi 256B, g 64B)
    const char* phiPtr = smem + SM_PHI + (gr * 8 + q * 2) * 4;
    const char* gaPtr  = smem + SM_GA + (gr * 260 + q) * 16;
    const char* gbPtr  = smem + SM_GB + (gr * 260 + q) * 16;

    ull pv = *(const ull*)phiPtr;
    ulonglong2 ga = *(const ulonglong2*)gaPtr;
    ulonglong2 gb = *(const ulonglong2*)gbPtr;

#pragma unroll 2
    for (int s = 0; s < 64; s++) {
        // prefetch next iteration (s=63 overreads into the next region: harmless, in-bounds)
        phiPtr += 256; gaPtr += 64; gbPtr += 64;
        ull pvn = *(const ull*)phiPtr;
        ulonglong2 gan = *(const ulonglong2*)gaPtr;
        ulonglong2 gbn = *(const ulonglong2*)gbPtr;

        float s0[4], s1v[4];
        mma_k8(s0, tA, tB, (uint32_t)pv);
        mma_k8(s1v, tA, tB, (uint32_t)(pv >> 32));
        uint32_t a0 = ex2h2(pack_h2(s0[0], s0[1]));
        uint32_t a1 = ex2h2(pack_h2(s0[2], s0[3]));
        uint32_t a2 = ex2h2(pack_h2(s1v[0], s1v[1]));
        uint32_t a3 = ex2h2(pack_h2(s1v[2], s1v[3]));
        float2 fA = __half22float2(__hadd2(u2h(a0), u2h(a2)));
        float2 fB = __half22float2(__hadd2(u2h(a1), u2h(a3)));
        seA += fA.x + fA.y;
        seB += fB.x + fB.y;
        mma_k16(c0, a0, a1, a2, a3, (uint32_t)ga.x, (uint32_t)(ga.x >> 32));
        mma_k16(c1, a0, a1, a2, a3, (uint32_t)ga.y, (uint32_t)(ga.y >> 32));
        mma_k16(c2, a0, a1, a2, a3, (uint32_t)gb.x, (uint32_t)(gb.x >> 32));
        mma_k16(c3, a0, a1, a2, a3, (uint32_t)gb.y, (uint32_t)(gb.y >> 32));

        pv = pvn; ga = gan; gb = gbn;
    }

    // row sums across the quad
    seA += __shfl_xor_sync(0xffffffffu, seA, 1);
    seA += __shfl_xor_sync(0xffffffffu, seA, 2);
    seB += __shfl_xor_sync(0xffffffffu, seB, 1);
    seB += __shfl_xor_sync(0xffffffffu, seB, 2);
    float invA = 1.0f / seA, invB = 1.0f / seB;

    __syncthreads();   // phi/g reads done; safe to overlay ag

    {
        int col = 2 * q;
        *(float2*)(ag + rA * 36 + col)      = make_float2(c0[0] * invA, c0[1] * invA);
        *(float2*)(ag + rB * 36 + col)      = make_float2(c0[2] * invB, c0[3] * invB);
        *(float2*)(ag + rA * 36 + col + 8)  = make_float2(c1[0] * invA, c1[1] * invA);
        *(float2*)(ag + rB * 36 + col + 8)  = make_float2(c1[2] * invB, c1[3] * invB);
        *(float2*)(ag + rA * 36 + col + 16) = make_float2(c2[0] * invA, c2[1] * invA);
        *(float2*)(ag + rB * 36 + col + 16) = make_float2(c2[2] * invB, c2[3] * invB);
        *(float2*)(ag + rA * 36 + col + 24) = make_float2(c3[0] * invA, c3[1] * invA);
        *(float2*)(ag + rB * 36 + col + 24) = make_float2(c3[2] * invB, c3[3] * invB);
    }
    __syncthreads();

    // Epilogue: thread (r = tid>>1, h = tid&1) -> out[h*32 .. +31][l0+r]
    int r = tid >> 1, h = tid & 1;
    ull rp[CG / 2];
    {
        const ulonglong2* apt = (const ulonglong2*)(ag + (size_t)r * 36);
#pragma unroll
        for (int p = 0; p < CG / 4; p++) {
            ulonglong2 v = apt[p];
            rp[2 * p] = v.x; rp[2 * p + 1] = v.y;
        }
    }
    float gamma = *gammap;
    const float* xp = x + ((size_t)n * CH + h * 32) * LL + l0 + r;
    float* op = out + ((size_t)n * CH + h * 32) * LL + l0 + r;
    const ulonglong2* w2 = (const ulonglong2*)wos;

#pragma unroll 4
    for (int i = 0; i < 32; i++) {
        int oc = h * 32 + i;
        ull s2 = 0ull;
#pragma unroll
        for (int p = 0; p < CG / 4; p++) {
            ulonglong2 wv = w2[oc * (CG / 4) + p];
            s2 = fma2(rp[2 * p], wv.x, s2);
            s2 = fma2(rp[2 * p + 1], wv.y, s2);
        }
        float2 sf = upk2(s2);
        op[(size_t)i * LL] = fmaf(gamma, sf.x + sf.y, xp[(size_t)i * LL]);
    }
}

// ---------------------------------------------------------------------------
extern "C" void kernel_launch(void* const* d_in, const int* in_sizes, int n_in,
                              void* d_out, int out_size) {
    const float* x       = (const float*)d_in[0];
    const float* w_theta = (const float*)d_in[1];
    const float* w_phi   = (const float*)d_in[2];
    const float* w_g     = (const float*)d_in[3];
    const float* w_o     = (const float*)d_in[4];
    const float* gammap  = (const float*)d_in[5];
    float* out = (float*)d_out;

    cudaFuncSetAttribute(attn_kernel, cudaFuncAttributeMaxDynamicSharedMemorySize,
                         SMEM_SZ);

    proj_fused_kernel<<<256, 256>>>(x, w_theta, w_phi, w_g);
    dim3 grid(LL / 256, NB);
    attn_kernel<<<grid, 512, SMEM_SZ>>>(x, w_o, gammap, out);
}

// round 8
// speedup vs baseline: 4.4724x; 1.2603x over previous
#include <cuda_runtime.h>
#include <cuda_fp16.h>
#include <cstdint>

// Problem constants
#define NB 16
#define CH 64
#define LL 4096   // H*W
#define DD 1024   // pooled locations
#define CK 8      // C>>3 (theta/phi channels)
#define CG 32     // C>>1 (g channels)

typedef unsigned long long ull;

// Scratch (device globals):
//  g_thetaH[n][l][q]  u32 = f16x2 {theta[2q], theta[2q+1]}, pre-scaled by log2(e)
//  g_phiP  [n][4096]  u32, phi fused-B layout: idx = s*64 + gr*8 + q*2 + u
//  g_gH    [n][j][s*4+q][elem] f16, elem -> d = 16s + {2q,2q+1,2q+8,2q+9}
__device__ __align__(16) uint32_t g_thetaH[NB * LL * 4];   // 4 MB
__device__ __align__(16) uint32_t g_phiP[NB * 4096];       // 256 KB
__device__ __align__(16) __half   g_gH[NB * CG * 1024];    // 1 MB

__device__ __forceinline__ ull pk2(float a, float b) {
    ull r; asm("mov.b64 %0, {%1, %2};" : "=l"(r) : "f"(a), "f"(b)); return r;
}
__device__ __forceinline__ float2 upk2(ull v) {
    float2 r; asm("mov.b64 {%0, %1}, %2;" : "=f"(r.x), "=f"(r.y) : "l"(v)); return r;
}
__device__ __forceinline__ ull fma2(ull a, ull b, ull c) {
    ull d; asm("fma.rn.f32x2 %0, %1, %2, %3;" : "=l"(d) : "l"(a), "l"(b), "l"(c)); return d;
}
__device__ __forceinline__ uint32_t pack_h2(float lo, float hi) {
    uint32_t r; asm("cvt.rn.f16x2.f32 %0, %1, %2;" : "=r"(r) : "f"(hi), "f"(lo)); return r;
}
__device__ __forceinline__ uint32_t ex2h2(uint32_t h) {
    uint32_t r; asm("ex2.approx.f16x2 %0, %1;" : "=r"(r) : "r"(h)); return r;
}

// MMA1: m16n8k8 f16, C = 0
__device__ __forceinline__ void mma_k8(float* d, uint32_t a0, uint32_t a1, uint32_t b0) {
    asm volatile(
        "mma.sync.aligned.m16n8k8.row.col.f32.f16.f16.f32 "
        "{%0,%1,%2,%3}, {%4,%5}, {%6}, {%7,%8,%9,%10};"
        : "=f"(d[0]), "=f"(d[1]), "=f"(d[2]), "=f"(d[3])
        : "r"(a0), "r"(a1), "r"(b0),
          "f"(0.f), "f"(0.f), "f"(0.f), "f"(0.f));
}
// MMA2: m16n8k16 f16, accumulate
__device__ __forceinline__ void mma_k16(float* c, uint32_t a0, uint32_t a1,
                                        uint32_t a2, uint32_t a3,
                                        uint32_t b0, uint32_t b1) {
    asm volatile(
        "mma.sync.aligned.m16n8k16.row.col.f32.f16.f16.f32 "
        "{%0,%1,%2,%3}, {%4,%5,%6,%7}, {%8,%9}, {%0,%1,%2,%3};"
        : "+f"(c[0]), "+f"(c[1]), "+f"(c[2]), "+f"(c[3])
        : "r"(a0), "r"(a1), "r"(a2), "r"(a3), "r"(b0), "r"(b1));
}

// ---------------------------------------------------------------------------
// Fused projection kernel (unchanged from R7).
// ---------------------------------------------------------------------------
__global__ void __launch_bounds__(256) proj_fused_kernel(
        const float* __restrict__ x, const float* __restrict__ w_theta,
        const float* __restrict__ w_phi, const float* __restrict__ w_g) {
    __shared__ ull wt2[CH * 4];
    __shared__ ull wp2[CH * 4];
    __shared__ ull wg2[CH * 16];
    int tid = threadIdx.x;
    for (int i = tid; i < CH * 4; i += 256) {
        int kp = i & 3, c = i >> 2;
        wt2[i] = pk2(w_theta[(2 * kp) * CH + c] * 1.4426950408889634f,
                     w_theta[(2 * kp + 1) * CH + c] * 1.4426950408889634f);
        wp2[i] = pk2(w_phi[(2 * kp) * CH + c], w_phi[(2 * kp + 1) * CH + c]);
    }
    for (int i = tid; i < CH * 16; i += 256) {
        int jp = i & 15, c = i >> 4;
        wg2[i] = pk2(w_g[(2 * jp) * CH + c], w_g[(2 * jp + 1) * CH + c]);
    }
    __syncthreads();

    int bid = blockIdx.x;
    int n = bid >> 4, yt = bid & 15;
    int b0 = tid & 1, b1 = (tid >> 1) & 1;
    int xpair = (tid >> 2) & 31;
    int yp = tid >> 7;
    int y = yt * 4 + yp * 2 + b1;
    int xc = xpair * 2 + b0;
    int l = y * 64 + xc;

    const float* xp = x + ((size_t)n * CH) * LL + l;

    ull at[4], ap[4], ag[16];
#pragma unroll
    for (int i = 0; i < 4; i++) { at[i] = 0ull; ap[i] = 0ull; }
#pragma unroll
    for (int i = 0; i < 16; i++) ag[i] = 0ull;

#pragma unroll 8
    for (int c = 0; c < CH; c++) {
        float xv = xp[(size_t)c * LL];
        ull vd = pk2(xv, xv);
#pragma unroll
        for (int kp = 0; kp < 4; kp++) at[kp] = fma2(wt2[c * 4 + kp], vd, at[kp]);
#pragma unroll
        for (int kp = 0; kp < 4; kp++) ap[kp] = fma2(wp2[c * 4 + kp], vd, ap[kp]);
#pragma unroll
        for (int jp = 0; jp < 16; jp++) ag[jp] = fma2(wg2[c * 16 + jp], vd, ag[jp]);
    }

    {
        float2 t0 = upk2(at[0]), t1 = upk2(at[1]), t2 = upk2(at[2]), t3 = upk2(at[3]);
        uint4 tq;
        tq.x = pack_h2(t0.x, t0.y);
        tq.y = pack_h2(t1.x, t1.y);
        tq.z = pack_h2(t2.x, t2.y);
        tq.w = pack_h2(t3.x, t3.y);
        *(uint4*)(g_thetaH + ((size_t)n * LL + l) * 4) = tq;
    }

    float phv[CK], gv[CG];
#pragma unroll
    for (int kp = 0; kp < 4; kp++) {
        float2 v = upk2(ap[kp]); phv[2 * kp] = v.x; phv[2 * kp + 1] = v.y;
    }
#pragma unroll
    for (int jp = 0; jp < 16; jp++) {
        float2 v = upk2(ag[jp]); gv[2 * jp] = v.x; gv[2 * jp + 1] = v.y;
    }
#pragma unroll
    for (int k = 0; k < CK; k++) {
        float v = phv[k];
        v = fmaxf(v, __shfl_xor_sync(0xffffffffu, v, 1));
        v = fmaxf(v, __shfl_xor_sync(0xffffffffu, v, 2));
        phv[k] = v;
    }
#pragma unroll
    for (int j = 0; j < CG; j++) {
        float v = gv[j];
        v = fmaxf(v, __shfl_xor_sync(0xffffffffu, v, 1));
        v = fmaxf(v, __shfl_xor_sync(0xffffffffu, v, 2));
        gv[j] = v;
    }

    if ((tid & 3) == 0) {
        int d = (yt * 2 + yp) * 32 + xpair;
        int s = d >> 4, gr = d & 7, u = (d >> 3) & 1;
        uint32_t* pdst = g_phiP + (size_t)n * 4096 + s * 64 + gr * 8 + u;
        pdst[0] = pack_h2(phv[0], phv[1]);
        pdst[2] = pack_h2(phv[2], phv[3]);
        pdst[4] = pack_h2(phv[4], phv[5]);
        pdst[6] = pack_h2(phv[6], phv[7]);

        int xu = (xpair >> 3) & 1;
        int qf = (xpair & 7) >> 1;
        int rb = xpair & 1;
        int elem = xu * 2 + rb;
        __half* gdst = g_gH + (size_t)n * CG * 1024;
#pragma unroll
        for (int j = 0; j < CG; j++)
            gdst[(j * 256 + s * 4 + qf) * 4 + elem] = __float2half_rn(gv[j]);
    }
}

// ---------------------------------------------------------------------------
// Attention kernel: tensor-core flash, fragment-native epilogue.
// Grid (16 L-tiles, 16 n) x 512 threads, 2 CTAs/SM.
// smem: phi 16K | gA 32.5K | gB 32.5K | wof 5K = 88064 B
//  wof[oc*20 + kq] = f16x2 {gamma*w_o[oc][2kq], gamma*w_o[oc][2kq+1]} (pad 20: conflict-free)
// ---------------------------------------------------------------------------
#define SM_PHI 0
#define SM_GA  16384
#define SM_GB  49664
#define SM_WOF 82944
#define SMEM_SZ 88064

#define ONES_H2 0x3C003C00u   // f16x2 {1.0, 1.0}

__global__ void __launch_bounds__(512, 2) attn_kernel(
        const float* __restrict__ x, const float* __restrict__ w_o,
        const float* __restrict__ gammap, float* __restrict__ out) {
    extern __shared__ char smem[];
    uint32_t* wof = (uint32_t*)(smem + SM_WOF);

    int tid = threadIdx.x;
    int n = blockIdx.y;
    int l0 = blockIdx.x * 256;
    float gamma = *gammap;

    // Cooperative fills
    {
        const uint4* s1 = (const uint4*)(g_phiP + (size_t)n * 4096);
        uint4* d1 = (uint4*)(smem + SM_PHI);
        for (int i = tid; i < 1024; i += 512) d1[i] = s1[i];
        const ull* s2 = (const ull*)(g_gH + (size_t)n * CG * 1024);
        ull* gA = (ull*)(smem + SM_GA);
        ull* gB = (ull*)(smem + SM_GB);
        for (int i = tid; i < 8192; i += 512) {
            ull v = s2[i];
            int j = i >> 8, sq = i & 255;
            int gr = j & 7, half = (j >> 3) & 1;
            ull* arr = (j < 16) ? gA : gB;
            arr[(gr * 260 + sq) * 2 + half] = v;
        }
        // w_o * gamma -> f16x2 pairs, padded stride 20
        const float2* s3 = (const float2*)w_o;
        for (int i = tid; i < 1024; i += 512) {
            int oc = i >> 4, kq = i & 15;
            float2 w = s3[oc * 16 + kq];
            wof[oc * 20 + kq] = pack_h2(w.x * gamma, w.y * gamma);
        }
    }

    int warp = tid >> 5, lane = tid & 31;
    int gr = lane >> 2, q = lane & 3;
    int rA = warp * 16 + gr;
    int rB = rA + 8;

    uint32_t tA = g_thetaH[((size_t)n * LL + l0 + rA) * 4 + q];
    uint32_t tB = g_thetaH[((size_t)n * LL + l0 + rB) * 4 + q];
    __syncthreads();

    float c0[4], c1[4], c2[4], c3[4], c4[4];
#pragma unroll
    for (int i = 0; i < 4; i++) {
        c0[i] = 0.f; c1[i] = 0.f; c2[i] = 0.f; c3[i] = 0.f; c4[i] = 0.f;
    }

    // mainloop pointers (advance per s: phi 256B, g 64B)
    const char* phiPtr = smem + SM_PHI + (gr * 8 + q * 2) * 4;
    const char* gaPtr  = smem + SM_GA + (gr * 260 + q) * 16;
    const char* gbPtr  = smem + SM_GB + (gr * 260 + q) * 16;

    ull pv = *(const ull*)phiPtr;
    ulonglong2 ga = *(const ulonglong2*)gaPtr;
    ulonglong2 gb = *(const ulonglong2*)gbPtr;

#pragma unroll 2
    for (int s = 0; s < 64; s++) {
        // prefetch next iteration (s=63 overread stays inside smem: harmless)
        phiPtr += 256; gaPtr += 64; gbPtr += 64;
        ull pvn = *(const ull*)phiPtr;
        ulonglong2 gan = *(const ulonglong2*)gaPtr;
        ulonglong2 gbn = *(const ulonglong2*)gbPtr;

        float s0[4], s1v[4];
        mma_k8(s0, tA, tB, (uint32_t)pv);
        mma_k8(s1v, tA, tB, (uint32_t)(pv >> 32));
        uint32_t a0 = ex2h2(pack_h2(s0[0], s0[1]));
        uint32_t a1 = ex2h2(pack_h2(s0[2], s0[3]));
        uint32_t a2 = ex2h2(pack_h2(s1v[0], s1v[1]));
        uint32_t a3 = ex2h2(pack_h2(s1v[2], s1v[3]));
        // attn_g accumulation (4 n-blocks) + row-sum via ones column
        mma_k16(c0, a0, a1, a2, a3, (uint32_t)ga.x, (uint32_t)(ga.x >> 32));
        mma_k16(c1, a0, a1, a2, a3, (uint32_t)ga.y, (uint32_t)(ga.y >> 32));
        mma_k16(c2, a0, a1, a2, a3, (uint32_t)gb.x, (uint32_t)(gb.x >> 32));
        mma_k16(c3, a0, a1, a2, a3, (uint32_t)gb.y, (uint32_t)(gb.y >> 32));
        mma_k16(c4, a0, a1, a2, a3, ONES_H2, ONES_H2);

        pv = pvn; ga = gan; gb = gbn;
    }

    // normalize: c4 columns all equal the row sums
    float invA = 1.0f / c4[0];
    float invB = 1.0f / c4[2];

    // pack normalized attn_g into epilogue A-fragments (k = j)
    uint32_t e0 = pack_h2(c0[0] * invA, c0[1] * invA);  // row rA, k 2q,2q+1
    uint32_t e1 = pack_h2(c0[2] * invB, c0[3] * invB);  // row rB
    uint32_t e2 = pack_h2(c1[0] * invA, c1[1] * invA);  // row rA, k 2q+8,2q+9
    uint32_t e3 = pack_h2(c1[2] * invB, c1[3] * invB);
    uint32_t e4 = pack_h2(c2[0] * invA, c2[1] * invA);  // k 16+2q
    uint32_t e5 = pack_h2(c2[2] * invB, c2[3] * invB);
    uint32_t e6 = pack_h2(c3[0] * invA, c3[1] * invA);  // k 24+2q
    uint32_t e7 = pack_h2(c3[2] * invB, c3[3] * invB);

    // Epilogue: D2[row, oc] = attn_g_norm[row, j] @ (gamma*w_o)^T[j, oc]; out = x + D2
    const uint32_t* wrow = wof + gr * 20;     // + ob*160 per block
#pragma unroll
    for (int ob = 0; ob < 8; ob++) {
        uint32_t b00 = wrow[ob * 160 + q];
        uint32_t b01 = wrow[ob * 160 + q + 4];
        uint32_t b10 = wrow[ob * 160 + q + 8];
        uint32_t b11 = wrow[ob * 160 + q + 12];
        float d2[4] = {0.f, 0.f, 0.f, 0.f};
        mma_k16(d2, e0, e1, e2, e3, b00, b01);
        mma_k16(d2, e4, e5, e6, e7, b10, b11);

        int oc = ob * 8 + 2 * q;
        const float* px = x + ((size_t)n * CH + oc) * LL + l0 + rA;
        float* po = out + ((size_t)n * CH + oc) * LL + l0 + rA;
        po[0]      = px[0]      + d2[0];   // (rA, oc)
        po[LL]     = px[LL]     + d2[1];   // (rA, oc+1)
        po[8]      = px[8]      + d2[2];   // (rB, oc)
        po[LL + 8] = px[LL + 8] + d2[3];   // (rB, oc+1)
    }
}

// ---------------------------------------------------------------------------
extern "C" void kernel_launch(void* const* d_in, const int* in_sizes, int n_in,
                              void* d_out, int out_size) {
    const float* x       = (const float*)d_in[0];
    const float* w_theta = (const float*)d_in[1];
    const float* w_phi   = (const float*)d_in[2];
    const float* w_g     = (const float*)d_in[3];
    const float* w_o     = (const float*)d_in[4];
    const float* gammap  = (const float*)d_in[5];
    float* out = (float*)d_out;

    cudaFuncSetAttribute(attn_kernel, cudaFuncAttributeMaxDynamicSharedMemorySize,
                         SMEM_SZ);

    proj_fused_kernel<<<256, 256>>>(x, w_theta, w_phi, w_g);
    dim3 grid(LL / 256, NB);
    attn_kernel<<<grid, 512, SMEM_SZ>>>(x, w_o, gammap, out);
}